// round 17
// baseline (speedup 1.0000x reference)
#include <cuda_runtime.h>
#include <cuda_fp16.h>
#include <math.h>

#define NTHR   512
#define NW     (NTHR / 32)        // 16 warps
#define HID    512
#define TENC   16384
#define NVOCAB 31
#define MAXLEN 100
#define EOSI   29
#define PADV   30.0f
#define NBUF   3
#define MAXBLK 256
#define PCACHE 64                 // fp16 enc rows pinned in smem per block
#define LDSTRIDE 32               // 128B padding stride

// ---------------- device scratch ----------------
__device__ __align__(16) __half2 g_enc16[(size_t)TENC * 512]; // fp16 copy of enc (33.5MB)
__device__ float g_ldot[NBUF][NVOCAB * LDSTRIDE];     // partial logit dots (summary part)
__device__ float g_tot[NBUF];                         // softmax denominators
__device__ __align__(16) float g_gh[2][3][HID];       // w_hh@h + b_hh (r,z,n), double buffered
__device__ __align__(16) float g_gx[NVOCAB][3 * HID]; // w_ih@embed[v] + b_ih
__device__ float g_lh[2][NVOCAB];                     // w_out[:,512:]@h + b_out, double buffered
__device__ volatile int g_count_b;                    // barrier arrival counter
__device__ volatile int g_gen;                        // barrier generation word

__device__ __forceinline__ float warp_allsum(float v) {
    #pragma unroll
    for (int o = 16; o; o >>= 1) v += __shfl_xor_sync(0xffffffffu, v, o);
    return v;
}
__device__ __forceinline__ int ld_acq(volatile int* p) {
    int v;
    asm volatile("ld.acquire.gpu.s32 %0, [%1];" : "=r"(v) : "l"((int*)p) : "memory");
    return v;
}
__device__ __forceinline__ void st_rel(volatile int* p, int v) {
    asm volatile("st.release.gpu.s32 [%0], %1;" :: "l"((int*)p), "r"(v) : "memory");
}
__device__ __forceinline__ int atom_add_acqrel(volatile int* p, int v) {
    int old;
    asm volatile("atom.acq_rel.gpu.global.add.s32 %0, [%1], %2;"
                 : "=r"(old) : "l"((int*)p), "r"(v) : "memory");
    return old;
}
__device__ __forceinline__ int imin(int a, int b) { return a < b ? a : b; }

// fused half2 pair -> two fp32 fma into d
#define H2FMA(d, u32, hx, hy) do {                                  \
    float2 _f = __half22float2(*(const __half2*)&(u32));            \
    d = fmaf(_f.x, (hx), fmaf(_f.y, (hy), d));                      \
} while (0)

// value half2 -> acc pair
#define H2ACC(accx, accy, u32, e) do {                              \
    float2 _f = __half22float2(*(const __half2*)&(u32));            \
    accx = fmaf((e), _f.x, accx); accy = fmaf((e), _f.y, accy);     \
} while (0)

// full row dot/acc helpers on 4 uint4 (keys kA,kB / values vA,vB)
#define ROW_DOT(d, kA, kB) do {                                     \
    float _d0 = 0.0f, _d1 = 0.0f;                                   \
    H2FMA(_d0, (kA).x, hA0.x, hA0.y); H2FMA(_d1, (kA).y, hA0.z, hA0.w); \
    H2FMA(_d0, (kA).z, hA1.x, hA1.y); H2FMA(_d1, (kA).w, hA1.z, hA1.w); \
    H2FMA(_d0, (kB).x, hB0.x, hB0.y); H2FMA(_d1, (kB).y, hB0.z, hB0.w); \
    H2FMA(_d0, (kB).z, hB1.x, hB1.y); H2FMA(_d1, (kB).w, hB1.z, hB1.w); \
    d = _d0 + _d1;                                                  \
} while (0)

#define ROW_ACC(vA, vB, e) do {                                     \
    H2ACC(accA0.x, accA0.y, (vA).x, e);                             \
    H2ACC(accA0.z, accA0.w, (vA).y, e);                             \
    H2ACC(accA1.x, accA1.y, (vA).z, e);                             \
    H2ACC(accA1.z, accA1.w, (vA).w, e);                             \
    H2ACC(accB0.x, accB0.y, (vB).x, e);                             \
    H2ACC(accB0.z, accB0.w, (vB).y, e);                             \
    H2ACC(accB1.x, accB1.y, (vB).z, e);                             \
    H2ACC(accB1.z, accB1.w, (vB).w, e);                             \
} while (0)

extern __shared__ float s_dyn[];   // [PCACHE*512 floats] fp16 rows | [31*512] w_out summary half

__global__ void __launch_bounds__(NTHR, 1)
decoder_kernel(const float* __restrict__ enc,     // [TENC, 1024] keys|values
               const float* __restrict__ embed,   // [31, 512]
               const float* __restrict__ w_ih,    // [1536, 512]
               const float* __restrict__ w_hh,    // [1536, 512]
               const float* __restrict__ b_ih,    // [1536]
               const float* __restrict__ b_hh,    // [1536]
               const float* __restrict__ w_out,   // [31, 1024]
               const float* __restrict__ b_out,   // [31]
               float* __restrict__ out)
{
    const int tid  = threadIdx.x;
    const int blk  = blockIdx.x;
    const int nblk = gridDim.x;
    const int wid  = tid >> 5;
    const int lane = tid & 31;
    const int base = lane * 4;
    const int l8   = lane * 8;

    __half2* s_enc16 = (__half2*)s_dyn;            // PCACHE rows, 512 half2 each
    float*   s_woutS = s_dyn + PCACHE * 512;       // [31][512] summary-half of w_out

    __shared__ __align__(16) float s_hh[HID];
    __shared__ __align__(16) float s_sum[HID];
    __shared__ __align__(16) float s_warp[8][HID];
    __shared__ float s_exp[128];
    __shared__ unsigned s_mask[4];
    __shared__ float s_red[NW];
    __shared__ int   s_best;

    float* out_logits = out;
    float* out_len    = out + MAXLEN * NVOCAB;
    float* out_attn   = out + MAXLEN * NVOCAB + 1;

    int ep = g_gen;

    auto grid_barrier = [&]() {
        ep++;
        __syncthreads();
        if (tid == 0) {
            int old = atom_add_acqrel(&g_count_b, 1);
            if (old == nblk - 1) {
                g_count_b = 0;
                st_rel(&g_gen, ep);
            } else {
                while (ld_acq(&g_gen) < ep) { }
            }
        }
        __syncthreads();
    };

    // ---------------- per-launch init ----------------
    s_hh[tid] = 0.0f;
    if (tid == 0) s_best = EOSI;
    if (tid < 4) s_mask[tid] = 0u;

    // near-uniform row partition; duty blocks 32..63 get the short rows
    const int nrows = TENC / nblk;
    const int extra = TENC - nrows * nblk;
    int t0, rows;
    if (blk < 32)      { t0 = nrows * blk + blk;  rows = nrows + 1; }
    else if (blk < 64) { t0 = nrows * blk + 32;   rows = nrows;     }
    else {
        const int b3 = imin(blk - 64, extra - 32);
        t0 = nrows * blk + 32 + b3;
        rows = nrows + ((blk - 64) < (extra - 32) ? 1 : 0);
    }
    const int t1 = t0 + rows;
    const int ts = t0 + PCACHE;

    // ---- convert OWN rows to fp16 (block-local; no cross-block dependency) ----
    {
        const float2* src = (const float2*)(enc + (size_t)t0 * 1024);
        __half2*      dst = g_enc16 + (size_t)t0 * 512;
        const int     n   = rows * 512;
        for (int i = tid; i < n; i += NTHR) {
            float2 f = __ldcg(src + i);
            dst[i] = __floats2half2_rn(f.x, f.y);
        }
    }
    __syncthreads();
    // pin first PCACHE rows (fp16) into smem
    {
        const uint4* src = (const uint4*)(g_enc16 + (size_t)t0 * 512);
        uint4*       dst = (uint4*)s_enc16;
        for (int i = tid; i < PCACHE * 128; i += NTHR) dst[i] = src[i];
    }
    // w_out summary half -> smem
    for (int i = tid; i < NVOCAB * HID; i += NTHR)
        s_woutS[i] = w_out[(size_t)(i >> 9) * 1024 + (i & 511)];

    if (blk == 0) {
        g_gh[0][0][tid] = b_hh[tid];
        g_gh[0][1][tid] = b_hh[tid + HID];
        g_gh[0][2][tid] = b_hh[tid + 2 * HID];
        if (wid == 1 && lane < NVOCAB) {
            #pragma unroll
            for (int b = 0; b < NBUF; ++b) g_ldot[b][lane * LDSTRIDE] = 0.0f;
        }
        if (tid == 0) { g_tot[0] = 0.0f; g_tot[1] = 0.0f; g_tot[2] = 0.0f; }
    }
    // gx table
    {
        const int gw = blk * NW + wid;
        for (int r = gw; r < NVOCAB * 3 * HID; r += nblk * NW) {
            const int v = r / (3 * HID);
            const int u = r - v * (3 * HID);
            const float* wrow = w_ih + (size_t)u * HID;
            const float* erow = embed + (size_t)v * HID;
            float a = 0.0f;
            #pragma unroll
            for (int m = 0; m < 4; ++m) {
                int c = base + m * 128;
                float4 w4 = *(const float4*)(wrow + c);
                float4 e4 = *(const float4*)(erow + c);
                a = fmaf(w4.x, e4.x, fmaf(w4.y, e4.y, fmaf(w4.z, e4.z, fmaf(w4.w, e4.w, a))));
            }
            a = warp_allsum(a);
            if (lane == 0) g_gx[v][u] = a + b_ih[u];
        }
    }
    __syncthreads();
    // PAD masks from fp32 keys
    for (int t = t0 + wid; t < t1; t += NW) {
        const float* row = enc + (size_t)t * (2 * HID);
        float4 k0 = __ldcg((const float4*)(row + base));
        float4 k1 = __ldcg((const float4*)(row + base + 128));
        float4 k2 = __ldcg((const float4*)(row + base + 256));
        float4 k3 = __ldcg((const float4*)(row + base + 384));
        int ok = (k0.x != PADV) | (k0.y != PADV) | (k0.z != PADV) | (k0.w != PADV)
               | (k1.x != PADV) | (k1.y != PADV) | (k1.z != PADV) | (k1.w != PADV)
               | (k2.x != PADV) | (k2.y != PADV) | (k2.z != PADV) | (k2.w != PADV)
               | (k3.x != PADV) | (k3.y != PADV) | (k3.z != PADV) | (k3.w != PADV);
        ok = __any_sync(0xffffffffu, ok);
        if (lane == 0 && ok) atomicOr(&s_mask[(t - t0) >> 5], 1u << ((t - t0) & 31));
    }
    int eos_step = MAXLEN;

    grid_barrier();

    const float scale = 0.04419417382415922f;   // 1/sqrt(512)

    for (int k = 0; k <= MAXLEN; ++k) {
        // ============ Phase A: epilogue of step k-1 ============
        if (k > 0) {
            const int p  = (k - 1) % NBUF;
            const int pl = (k - 1) & 1;
            const float inv_total = 1.0f / g_tot[p];

            const int pg = k & 1;
            const float gh0 = g_gh[pg][0][tid];
            const float gh1 = g_gh[pg][1][tid];
            const float gh2 = g_gh[pg][2][tid];

            if (wid == 0) {
                float lg = -1e30f;
                if (lane < NVOCAB)
                    lg = g_ldot[p][lane * LDSTRIDE] * inv_total + g_lh[pl][lane];
                unsigned kb = __float_as_uint(lg);
                kb = (kb & 0x80000000u) ? ~kb : (kb | 0x80000000u);
                unsigned long long pk = ((unsigned long long)kb << 6) | (unsigned)(63 - lane);
                #pragma unroll
                for (int o = 16; o; o >>= 1) {
                    unsigned long long q = __shfl_xor_sync(0xffffffffu, pk, o);
                    if (q > pk) pk = q;
                }
                if (lane == 0) {
                    int best = 63 - (int)(pk & 63u);
                    s_best = best;
                    if (blk == 0 && best == EOSI && eos_step == MAXLEN) eos_step = k - 1;
                }
                if (blk == 0 && lane < NVOCAB)
                    out_logits[(k - 1) * NVOCAB + lane] = lg;
            } else if (wid == 1) {
                if (blk == 0) {
                    const int zb = (k + 1) % NBUF;
                    if (lane < NVOCAB) g_ldot[zb][lane * LDSTRIDE] = 0.0f;
                    if (lane == 31) g_tot[zb] = 0.0f;
                }
            } else {
                for (int t = t0 + (tid - 64); t < t1; t += NTHR - 64)
                    out_attn[(size_t)(k - 1) * TENC + t] = s_exp[t - t0] * inv_total;
            }
            __syncthreads();

            if (k == MAXLEN) break;

            const float* gx = g_gx[s_best];
            float r = 1.0f / (1.0f + __expf(-(gx[tid]           + gh0)));
            float z = 1.0f / (1.0f + __expf(-(gx[tid + HID]     + gh1)));
            float n = tanhf(gx[tid + 2 * HID] + r * gh2);
            s_hh[tid] = (1.0f - z) * n + z * s_hh[tid];
            __syncthreads();
        } else {
            const float* gx = g_gx[EOSI];
            float r = 1.0f / (1.0f + __expf(-(gx[tid]           + g_gh[0][0][tid])));
            float z = 1.0f / (1.0f + __expf(-(gx[tid + HID]     + g_gh[0][1][tid])));
            float n = tanhf(gx[tid + 2 * HID] + r * g_gh[0][2][tid]);
            s_hh[tid] = (1.0f - z) * n;
            __syncthreads();
        }

        // ============ Phase B: attention sweep (fp16 enc) ============
        float4 hA0 = *(const float4*)(s_hh + l8);
        float4 hA1 = *(const float4*)(s_hh + l8 + 4);
        float4 hB0 = *(const float4*)(s_hh + 256 + l8);
        float4 hB1 = *(const float4*)(s_hh + 256 + l8 + 4);
        float4 h0 = *(const float4*)(s_hh + base);
        float4 h1 = *(const float4*)(s_hh + base + 128);
        float4 h2 = *(const float4*)(s_hh + base + 256);
        float4 h3 = *(const float4*)(s_hh + base + 384);

        // lh duty: blocks 32..62, warp 0
        if (wid == 0 && blk >= 32 && blk < 32 + NVOCAB) {
            const int v = blk - 32;
            const float* wrow = w_out + (size_t)v * 1024 + HID;
            float dot = 0.0f;
            float4 w4;
            w4 = *(const float4*)(wrow + base);
            dot = fmaf(w4.x, h0.x, fmaf(w4.y, h0.y, fmaf(w4.z, h0.z, fmaf(w4.w, h0.w, dot))));
            w4 = *(const float4*)(wrow + base + 128);
            dot = fmaf(w4.x, h1.x, fmaf(w4.y, h1.y, fmaf(w4.z, h1.z, fmaf(w4.w, h1.w, dot))));
            w4 = *(const float4*)(wrow + base + 256);
            dot = fmaf(w4.x, h2.x, fmaf(w4.y, h2.y, fmaf(w4.z, h2.z, fmaf(w4.w, h2.w, dot))));
            w4 = *(const float4*)(wrow + base + 384);
            dot = fmaf(w4.x, h3.x, fmaf(w4.y, h3.y, fmaf(w4.z, h3.z, fmaf(w4.w, h3.w, dot))));
            dot = warp_allsum(dot);
            if (lane == 0) g_lh[k & 1][v] = dot + b_out[v];
        }

        float4 accA0 = {0,0,0,0}, accA1 = {0,0,0,0}, accB0 = {0,0,0,0}, accB1 = {0,0,0,0};
        float esum = 0.0f;

        // ---- streamed rows: 2 rows/iter, fused K+V fp16 (8 LDG.128 in flight) ----
        for (int ta = ts + wid; ta < t1; ta += NW * 2) {
            const int tb  = ta + NW;
            const int bok = (tb < t1);
            const int trb = bok ? tb : ta;
            const uint4* ra = (const uint4*)(g_enc16 + (size_t)ta  * 512);
            const uint4* rb = (const uint4*)(g_enc16 + (size_t)trb * 512);
            uint4 akA = __ldcg(ra + lane);
            uint4 akB = __ldcg(ra + 32 + lane);
            uint4 avA = __ldcg(ra + 64 + lane);
            uint4 avB = __ldcg(ra + 96 + lane);
            uint4 bkA = __ldcg(rb + lane);
            uint4 bkB = __ldcg(rb + 32 + lane);
            uint4 bvA = __ldcg(rb + 64 + lane);
            uint4 bvB = __ldcg(rb + 96 + lane);

            float da, db;
            ROW_DOT(da, akA, akB);
            ROW_DOT(db, bkA, bkB);
            // interleaved reduction chains
            #pragma unroll
            for (int o = 16; o; o >>= 1) {
                da += __shfl_xor_sync(0xffffffffu, da, o);
                db += __shfl_xor_sync(0xffffffffu, db, o);
            }
            const int ia = ta - t0, ib = trb - t0;
            const unsigned ma = (s_mask[ia >> 5] >> (ia & 31)) & 1u;
            const unsigned mb = (s_mask[ib >> 5] >> (ib & 31)) & 1u;
            float ea = ma ? __expf(da * scale) : 0.0f;
            float eb = (bok && mb) ? __expf(db * scale) : 0.0f;
            if (lane == 0) {
                s_exp[ia] = ea;
                if (bok) s_exp[ib] = eb;
                esum += ea + eb;
            }
            ROW_ACC(avA, avB, ea);
            ROW_ACC(bvA, bvB, eb);
        }

        // ---- pinned rows (smem, fp16), 2 rows/iter ----
        for (int ta = t0 + wid; ta < ts; ta += NW * 2) {
            const int tb  = ta + NW;
            const int bok = (tb < ts);
            const int trb = bok ? tb : ta;
            const uint4* ra = (const uint4*)(s_enc16 + (size_t)(ta - t0)  * 512);
            const uint4* rb = (const uint4*)(s_enc16 + (size_t)(trb - t0) * 512);
            uint4 akA = ra[lane];
            uint4 akB = ra[32 + lane];
            uint4 avA = ra[64 + lane];
            uint4 avB = ra[96 + lane];
            uint4 bkA = rb[lane];
            uint4 bkB = rb[32 + lane];
            uint4 bvA = rb[64 + lane];
            uint4 bvB = rb[96 + lane];

            float da, db;
            ROW_DOT(da, akA, akB);
            ROW_DOT(db, bkA, bkB);
            #pragma unroll
            for (int o = 16; o; o >>= 1) {
                da += __shfl_xor_sync(0xffffffffu, da, o);
                db += __shfl_xor_sync(0xffffffffu, db, o);
            }
            const int ia = ta - t0, ib = trb - t0;
            const unsigned ma = (s_mask[ia >> 5] >> (ia & 31)) & 1u;
            const unsigned mb = (s_mask[ib >> 5] >> (ib & 31)) & 1u;
            float ea = ma ? __expf(da * scale) : 0.0f;
            float eb = (bok && mb) ? __expf(db * scale) : 0.0f;
            if (lane == 0) {
                s_exp[ia] = ea;
                if (bok) s_exp[ib] = eb;
                esum += ea + eb;
            }
            ROW_ACC(avA, avB, ea);
            ROW_ACC(bvA, bvB, eb);
        }

        // gh duty: blocks 32..127, one dot per warp (fp32)
        if (blk >= 32 && blk < 128) {
            const int d  = (blk - 32) * NW + wid;
            const int g  = d >> 9;
            const int j  = d & 511;
            const int pn = (k + 1) & 1;
            const float* ur = w_hh + (size_t)(g * HID + j) * HID;
            float a = 0.0f;
            #pragma unroll
            for (int m = 0; m < 4; ++m) {
                int c = base + m * 128;
                float4 hx = *(const float4*)(s_hh + c);
                float4 u4 = *(const float4*)(ur + c);
                a = fmaf(hx.x, u4.x, fmaf(hx.y, u4.y, fmaf(hx.z, u4.z, fmaf(hx.w, u4.w, a))));
            }
            a = warp_allsum(a);
            if (lane == 0) g_gh[pn][g][j] = a + b_hh[g * HID + j];
        }

        // ---- merge: two-phase staging (fp16 lane layout) ----
        if (lane == 0) s_red[wid] = esum;
        if (wid < 8) {
            *(float4*)&s_warp[wid][l8]           = accA0;
            *(float4*)&s_warp[wid][l8 + 4]       = accA1;
            *(float4*)&s_warp[wid][256 + l8]     = accB0;
            *(float4*)&s_warp[wid][256 + l8 + 4] = accB1;
        }
        __syncthreads();
        if (wid >= 8) {
            float* bdst = s_warp[wid - 8];
            float4 t;
            t = *(float4*)&bdst[l8];
            t.x += accA0.x; t.y += accA0.y; t.z += accA0.z; t.w += accA0.w;
            *(float4*)&bdst[l8] = t;
            t = *(float4*)&bdst[l8 + 4];
            t.x += accA1.x; t.y += accA1.y; t.z += accA1.z; t.w += accA1.w;
            *(float4*)&bdst[l8 + 4] = t;
            t = *(float4*)&bdst[256 + l8];
            t.x += accB0.x; t.y += accB0.y; t.z += accB0.z; t.w += accB0.w;
            *(float4*)&bdst[256 + l8] = t;
            t = *(float4*)&bdst[256 + l8 + 4];
            t.x += accB1.x; t.y += accB1.y; t.z += accB1.z; t.w += accB1.w;
            *(float4*)&bdst[256 + l8 + 4] = t;
        }
        __syncthreads();
        {
            float colsum = 0.0f;
            #pragma unroll
            for (int w8 = 0; w8 < 8; ++w8) colsum += s_warp[w8][tid];
            s_sum[tid] = colsum;
        }
        __syncthreads();

        // ---- partial logit dots (fp32) ----
        const int bb = k % NBUF;
        for (int v = wid; v < NVOCAB; v += NW) {
            const float* wrow = s_woutS + v * HID;
            float dot = 0.0f;
            #pragma unroll
            for (int m = 0; m < 4; ++m) {
                int c = base + m * 128;
                float4 w4 = *(const float4*)(wrow + c);
                float4 x4 = *(const float4*)(s_sum + c);
                dot = fmaf(w4.x, x4.x, fmaf(w4.y, x4.y, fmaf(w4.z, x4.z, fmaf(w4.w, x4.w, dot))));
            }
            dot = warp_allsum(dot);
            if (lane == 0) atomicAdd(&g_ldot[bb][v * LDSTRIDE], dot);
        }
        if (tid == 0) {
            float tot = 0.0f;
            #pragma unroll
            for (int w8 = 0; w8 < NW; ++w8) tot += s_red[w8];
            atomicAdd(&g_tot[bb], tot);
        }

        grid_barrier();
    }

    if (blk == 0 && tid == 0) out_len[0] = (float)eos_step;
}

extern "C" void kernel_launch(void* const* d_in, const int* in_sizes, int n_in,
                              void* d_out, int out_size) {
    const float* enc   = (const float*)d_in[0];
    const float* embed = (const float*)d_in[2];
    const float* w_ih  = (const float*)d_in[3];
    const float* w_hh  = (const float*)d_in[4];
    const float* b_ih  = (const float*)d_in[5];
    const float* b_hh  = (const float*)d_in[6];
    const float* w_out = (const float*)d_in[7];
    const float* b_out = (const float*)d_in[8];
    (void)in_sizes; (void)n_in; (void)out_size;

    const int smem_dyn = (PCACHE * 512 + NVOCAB * HID) * sizeof(float);   // 194560 B
    static int nblk = 0;
    if (!nblk) {
        cudaFuncSetAttribute(decoder_kernel,
                             cudaFuncAttributeMaxDynamicSharedMemorySize, smem_dyn);
        int dev = 0;
        cudaGetDevice(&dev);
        int sms = 0;
        cudaDeviceGetAttribute(&sms, cudaDevAttrMultiProcessorCount, dev);
        nblk = (sms >= 128 && sms <= MAXBLK) ? sms : 148;
    }
    decoder_kernel<<<nblk, NTHR, smem_dyn>>>(enc, embed, w_ih, w_hh, b_ih, b_hh,
                                             w_out, b_out, (float*)d_out);
}